// round 6
// baseline (speedup 1.0000x reference)
#include <cuda_runtime.h>
#include <cuda_bf16.h>
#include <cstdint>

#define D      128      // D_IN = D_OUT
#define NMAX   100000
#define EMAX   1600000

// Scratch (device globals; no allocation allowed)
__device__ __nv_bfloat16 g_xh[NMAX * D];      // x hi (bf16)
__device__ __nv_bfloat16 g_xl[NMAX * D];      // x lo (residual bf16)
__device__ float         g_support[NMAX * D]; // support = A @ x
__device__ int           g_ecursor;           // edge-chunk work-stealing cursor

// ============================================================================
// PTX helpers (base ISA: cp.async / ldmatrix / mma.sync)
// ============================================================================
__device__ __forceinline__ uint32_t smem_to_u32(const void* p) {
    uint32_t a;
    asm("{ .reg .u64 t; cvta.to.shared.u64 t, %1; cvt.u32.u64 %0, t; }"
        : "=r"(a) : "l"(p));
    return a;
}
#define CP_ASYNC16(dst, src, sz) \
    asm volatile("cp.async.cg.shared.global [%0], [%1], 16, %2;" \
        :: "r"(dst), "l"(src), "r"(sz))
#define CP_COMMIT() asm volatile("cp.async.commit_group;" ::: "memory")
#define CP_WAIT1()  asm volatile("cp.async.wait_group 1;"  ::: "memory")

#define LDSM_X4(r0,r1,r2,r3,addr) \
    asm volatile("ldmatrix.sync.aligned.m8n8.x4.shared.b16 {%0,%1,%2,%3}, [%4];" \
        : "=r"(r0), "=r"(r1), "=r"(r2), "=r"(r3) : "r"(addr))
#define LDSM_X4T(r0,r1,r2,r3,addr) \
    asm volatile("ldmatrix.sync.aligned.m8n8.x4.trans.shared.b16 {%0,%1,%2,%3}, [%4];" \
        : "=r"(r0), "=r"(r1), "=r"(r2), "=r"(r3) : "r"(addr))

#define MMA16816(c, a, b) \
    asm volatile("mma.sync.aligned.m16n8k16.row.col.f32.bf16.bf16.f32 " \
        "{%0,%1,%2,%3}, {%4,%5,%6,%7}, {%8,%9}, {%0,%1,%2,%3};" \
        : "+f"((c)[0]), "+f"((c)[1]), "+f"((c)[2]), "+f"((c)[3]) \
        : "r"((a)[0]), "r"((a)[1]), "r"((a)[2]), "r"((a)[3]), \
          "r"((b)[0]), "r"((b)[1]))

// RED without a memory clobber: volatile keeps it, data deps order it after
// the gather, and the compiler is free to pipeline batches across iterations.
#define RED4(p, a, b, c, dd) \
    asm volatile("red.global.add.v4.f32 [%0], {%1, %2, %3, %4};" \
        :: "l"(p), "f"(a), "f"(b), "f"(c), "f"(dd))

// bf16 hi/lo split of a float4 -> two packed 8-byte words
__device__ __forceinline__ void split4(float4 v, uint64_t& hw, uint64_t& lw) {
    __nv_bfloat162 h0 = __floats2bfloat162_rn(v.x, v.y);
    __nv_bfloat162 h1 = __floats2bfloat162_rn(v.z, v.w);
    float r0 = v.x - __bfloat162float(h0.x);
    float r1 = v.y - __bfloat162float(h0.y);
    float r2 = v.z - __bfloat162float(h1.x);
    float r3 = v.w - __bfloat162float(h1.y);
    __nv_bfloat162 l0 = __floats2bfloat162_rn(r0, r1);
    __nv_bfloat162 l1 = __floats2bfloat162_rn(r2, r3);
    hw = (uint64_t)*(uint32_t*)&h0 | ((uint64_t)*(uint32_t*)&h1 << 32);
    lw = (uint64_t)*(uint32_t*)&l0 | ((uint64_t)*(uint32_t*)&l1 << 32);
}
#define STS64(smem_addr, val) \
    asm volatile("st.shared.b64 [%0], %1;" :: "r"(smem_addr), "l"(val) : "memory")

// ============================================================================
// Kernel 1: split x -> bf16 hi/lo, zero support, reset edge cursor
//   (n4 == N*32 covers both x float4s and support float4s)
// ============================================================================
__global__ void convert_kernel(const float* __restrict__ x, int n4) {
    int i = blockIdx.x * blockDim.x + threadIdx.x;
    if (i == 0) g_ecursor = 0;
    if (i >= n4) return;
    float4 v = reinterpret_cast<const float4*>(x)[i];
    uint64_t hw, lw;
    split4(v, hw, lw);
    reinterpret_cast<uint64_t*>(g_xh)[i] = hw;
    reinterpret_cast<uint64_t*>(g_xl)[i] = lw;
    reinterpret_cast<float4*>(g_support)[i] = make_float4(0.f, 0.f, 0.f, 0.f);
}

// ============================================================================
// Kernel 2: FUSED  [ gemm1: out = x@W1 + b  ||  scatter: support += A@x ]
//   grid = 148 CTAs, 256 threads, 192KB smem.
//   CTAs [0, G_GEMM) run gemm tiles first, then steal edge chunks.
//   CTAs [G_GEMM, 148) scatter edge chunks from a global cursor.
// ============================================================================
#define GT        256
#define G_GEMM    24
#define NCTA      148
#define ECHUNK    2048                 // edges per steal (256 per warp)
#define AS_OFF(buf,hl) ((uint32_t)(((buf)<<1 | (hl)) * 32768))
#define BS_OFF(hl)     ((uint32_t)(131072 + (hl) * 32768))
#define SM_TOTAL       196608

__device__ __forceinline__ void load_A_tile_g(uint32_t smem_base, int buf,
                                              int node0, int N, int tid) {
#pragma unroll
    for (int i = 0; i < 8; i++) {
        int idx  = tid + (i << 8);
        int row  = idx >> 4;
        int cc   = idx & 15;
        int node = node0 + row;
        uint32_t sz    = (node < N) ? 16u : 0u;
        uint32_t chunk = (uint32_t)(cc ^ (row & 7));
        uint32_t doff  = (uint32_t)row * 256u + chunk * 16u;
        const __nv_bfloat16* sh = g_xh + (size_t)node * D + cc * 8;
        const __nv_bfloat16* sl = g_xl + (size_t)node * D + cc * 8;
        CP_ASYNC16(smem_base + AS_OFF(buf, 0) + doff, sh, sz);
        CP_ASYNC16(smem_base + AS_OFF(buf, 1) + doff, sl, sz);
    }
}

// one warp processes edges [e0, e1): 4-wide batched gather + RED
__device__ __forceinline__ void scatter_edges(const int* __restrict__ esrc,
                                              const int* __restrict__ edst,
                                              const float* __restrict__ eval_,
                                              const float* __restrict__ x,
                                              int e0, int e1, int lane) {
    const float4* x4 = reinterpret_cast<const float4*>(x);
    int e = e0;
    for (; e + 4 <= e1; e += 4) {
        int   s0 = esrc[e],   s1 = esrc[e+1],   s2 = esrc[e+2],   s3 = esrc[e+3];
        int   d0 = edst[e],   d1 = edst[e+1],   d2 = edst[e+2],   d3 = edst[e+3];
        float v0 = eval_[e],  v1 = eval_[e+1],  v2 = eval_[e+2],  v3 = eval_[e+3];
        float4 a0 = x4[(size_t)s0 * 32 + lane];
        float4 a1 = x4[(size_t)s1 * 32 + lane];
        float4 a2 = x4[(size_t)s2 * 32 + lane];
        float4 a3 = x4[(size_t)s3 * 32 + lane];
        RED4(g_support + (size_t)d0 * D + lane*4, a0.x*v0, a0.y*v0, a0.z*v0, a0.w*v0);
        RED4(g_support + (size_t)d1 * D + lane*4, a1.x*v1, a1.y*v1, a1.z*v1, a1.w*v1);
        RED4(g_support + (size_t)d2 * D + lane*4, a2.x*v2, a2.y*v2, a2.z*v2, a2.w*v2);
        RED4(g_support + (size_t)d3 * D + lane*4, a3.x*v3, a3.y*v3, a3.z*v3, a3.w*v3);
    }
    for (; e < e1; e++) {
        int s0 = esrc[e]; int d0 = edst[e]; float v0 = eval_[e];
        float4 a0 = x4[(size_t)s0 * 32 + lane];
        RED4(g_support + (size_t)d0 * D + lane*4, a0.x*v0, a0.y*v0, a0.z*v0, a0.w*v0);
    }
}

__global__ __launch_bounds__(GT, 1)
void fused_kernel(const float* __restrict__ x,
                  const int*   __restrict__ esrc,
                  const int*   __restrict__ edst,
                  const float* __restrict__ eval_,
                  const float* __restrict__ W,
                  const float* __restrict__ bias,
                  float* __restrict__ out,
                  int N, int E) {
    const int tid  = threadIdx.x;
    const int lane = tid & 31;
    const int wid  = tid >> 5;
    const int bid  = blockIdx.x;

    if (bid < G_GEMM) {
        // ---------------- GEMM role: out = x @ W1 + b ----------------
        extern __shared__ char smem[];
        uint32_t smem_base = smem_to_u32(smem);
        const int warp_m = (wid & 3) << 5;
        const int warp_n = (wid >> 2) << 6;
        const int num_tiles = (N + 127) >> 7;

        // B = W[0:128][:] hi/lo
#pragma unroll
        for (int j = 0; j < 32; j++) {
            int idx = tid + (j << 8);
            int k   = idx >> 6;
            int n   = (idx & 63) << 1;
            const float* wp = W + (size_t)k * 128 + n;
            float w0 = wp[0], w1 = wp[1];
            __nv_bfloat162 h = __floats2bfloat162_rn(w0, w1);
            float q0 = w0 - __bfloat162float(h.x);
            float q1 = w1 - __bfloat162float(h.y);
            __nv_bfloat162 l = __floats2bfloat162_rn(q0, q1);
            uint32_t boff = (uint32_t)k * 256u
                          + (uint32_t)(((n >> 3) ^ (k & 7)) << 4)
                          + (uint32_t)((n & 7) << 1);
            *reinterpret_cast<uint32_t*>(smem + BS_OFF(0) + boff) = *(uint32_t*)&h;
            *reinterpret_cast<uint32_t*>(smem + BS_OFF(1) + boff) = *(uint32_t*)&l;
        }

        int item = bid;
        int buf = 0;
        if (item < num_tiles) load_A_tile_g(smem_base, 0, item << 7, N, tid);
        CP_COMMIT();

        for (; item < num_tiles; item += G_GEMM) {
            const int node0 = item << 7;
            int next = item + G_GEMM;
            if (next < num_tiles)
                load_A_tile_g(smem_base, buf ^ 1, next << 7, N, tid);
            CP_COMMIT();
            CP_WAIT1();
            __syncthreads();

            float acc[2][8][4];
#pragma unroll
            for (int mi = 0; mi < 2; mi++)
#pragma unroll
                for (int ni = 0; ni < 8; ni++)
#pragma unroll
                    for (int q = 0; q < 4; q++) acc[mi][ni][q] = 0.f;

#pragma unroll
            for (int ks = 0; ks < 8; ks++) {
                uint32_t ah[2][4], al[2][4];
#pragma unroll
                for (int mi = 0; mi < 2; mi++) {
                    int row = warp_m + (mi << 4) + (lane & 15);
                    int cb  = (ks << 1) + (lane >> 4);
                    uint32_t addr = smem_base + AS_OFF(buf, 0)
                                  + (uint32_t)row * 256u
                                  + (uint32_t)((cb ^ (row & 7)) << 4);
                    LDSM_X4(ah[mi][0], ah[mi][1], ah[mi][2], ah[mi][3], addr);
                    LDSM_X4(al[mi][0], al[mi][1], al[mi][2], al[mi][3], addr + 32768u);
                }
                uint32_t bh[8][2], bl[8][2];
#pragma unroll
                for (int nj = 0; nj < 4; nj++) {
                    int row = (ks << 4) + (lane & 15);
                    int cb  = (warp_n >> 3) + (nj << 1) + (lane >> 4);
                    uint32_t addr = smem_base + BS_OFF(0)
                                  + (uint32_t)row * 256u
                                  + (uint32_t)((cb ^ (row & 7)) << 4);
                    LDSM_X4T(bh[2*nj][0], bh[2*nj][1], bh[2*nj+1][0], bh[2*nj+1][1], addr);
                    LDSM_X4T(bl[2*nj][0], bl[2*nj][1], bl[2*nj+1][0], bl[2*nj+1][1],
                             addr + 32768u);
                }
#pragma unroll
                for (int mi = 0; mi < 2; mi++)
#pragma unroll
                    for (int ni = 0; ni < 8; ni++) {
                        MMA16816(acc[mi][ni], ah[mi], bh[ni]);
                        MMA16816(acc[mi][ni], ah[mi], bl[ni]);
                        MMA16816(acc[mi][ni], al[mi], bh[ni]);
                    }
            }

#pragma unroll
            for (int ni = 0; ni < 8; ni++) {
                int col = warp_n + (ni << 3) + ((lane & 3) << 1);
                float b0 = bias[col], b1 = bias[col + 1];
#pragma unroll
                for (int mi = 0; mi < 2; mi++) {
                    int r = warp_m + (mi << 4) + (lane >> 2);
                    int node = node0 + r;
                    if (node < N) {
                        float2 v = make_float2(acc[mi][ni][0] + b0, acc[mi][ni][1] + b1);
                        *reinterpret_cast<float2*>(out + (size_t)node * D + col) = v;
                    }
                    int node2 = node + 8;
                    if (node2 < N) {
                        float2 v = make_float2(acc[mi][ni][2] + b0, acc[mi][ni][3] + b1);
                        *reinterpret_cast<float2*>(out + (size_t)node2 * D + col) = v;
                    }
                }
            }
            __syncthreads();
            buf ^= 1;
        }
        // fall through to edge stealing
    }

    // ---------------- scatter role (all CTAs eventually) ----------------
    __shared__ int s_base;
    for (;;) {
        if (tid == 0) s_base = atomicAdd(&g_ecursor, ECHUNK);
        __syncthreads();
        int base = s_base;
        __syncthreads();
        if (base >= E) break;
        int we0 = base + wid * (ECHUNK / 8);
        int we1 = min(we0 + (ECHUNK / 8), E);
        if (we0 < E) scatter_edges(esrc, edst, eval_, x, we0, we1, lane);
    }
}

// ============================================================================
// Kernel 3: out += support @ W2   (inline fp32 -> split-bf16 of support)
//   A single-buffered (hi/lo 64KB), B = W[128:256] hi/lo (64KB). 128KB smem.
// ============================================================================
#define AS3(hl)  ((uint32_t)((hl) * 32768))
#define BS3(hl)  ((uint32_t)(65536 + (hl) * 32768))
#define SM3_TOTAL 131072

__global__ __launch_bounds__(GT, 1)
void gemm2_kernel(const float* __restrict__ W,
                  float* __restrict__ out,
                  int N) {
    extern __shared__ char smem[];
    uint32_t smem_base = smem_to_u32(smem);
    const int tid  = threadIdx.x;
    const int lane = tid & 31;
    const int wid  = tid >> 5;
    const int warp_m = (wid & 3) << 5;
    const int warp_n = (wid >> 2) << 6;
    const int num_tiles = (N + 127) >> 7;

    // B = W[128:256][:] hi/lo
#pragma unroll
    for (int j = 0; j < 32; j++) {
        int idx = tid + (j << 8);
        int k   = idx >> 6;
        int n   = (idx & 63) << 1;
        const float* wp = W + (size_t)(128 + k) * 128 + n;
        float w0 = wp[0], w1 = wp[1];
        __nv_bfloat162 h = __floats2bfloat162_rn(w0, w1);
        float q0 = w0 - __bfloat162float(h.x);
        float q1 = w1 - __bfloat162float(h.y);
        __nv_bfloat162 l = __floats2bfloat162_rn(q0, q1);
        uint32_t boff = (uint32_t)k * 256u
                      + (uint32_t)(((n >> 3) ^ (k & 7)) << 4)
                      + (uint32_t)((n & 7) << 1);
        *reinterpret_cast<uint32_t*>(smem + BS3(0) + boff) = *(uint32_t*)&h;
        *reinterpret_cast<uint32_t*>(smem + BS3(1) + boff) = *(uint32_t*)&l;
    }

    for (int item = blockIdx.x; item < num_tiles; item += gridDim.x) {
        const int node0 = item << 7;

        // fill A from fp32 support with inline split: 4096 float4 / 256 thr
        __syncthreads();
#pragma unroll
        for (int j = 0; j < 16; j++) {
            int idx  = tid + (j << 8);         // 0..4095
            int row  = idx >> 5;               // 0..127
            int cc   = idx & 31;               // float4 within row
            int node = node0 + row;
            float4 v = (node < N)
                ? reinterpret_cast<const float4*>(g_support)[(size_t)node * 32 + cc]
                : make_float4(0.f, 0.f, 0.f, 0.f);
            uint64_t hw, lw;
            split4(v, hw, lw);
            int ch = cc >> 1;                   // 16B chunk
            uint32_t off = (uint32_t)row * 256u
                         + (uint32_t)((ch ^ (row & 7)) << 4)
                         + (uint32_t)((cc & 1) << 3);
            STS64(smem_base + AS3(0) + off, hw);
            STS64(smem_base + AS3(1) + off, lw);
        }
        __syncthreads();

        float acc[2][8][4];
#pragma unroll
        for (int mi = 0; mi < 2; mi++)
#pragma unroll
            for (int ni = 0; ni < 8; ni++)
#pragma unroll
                for (int q = 0; q < 4; q++) acc[mi][ni][q] = 0.f;

#pragma unroll
        for (int ks = 0; ks < 8; ks++) {
            uint32_t ah[2][4], al[2][4];
#pragma unroll
            for (int mi = 0; mi < 2; mi++) {
                int row = warp_m + (mi << 4) + (lane & 15);
                int cb  = (ks << 1) + (lane >> 4);
                uint32_t addr = smem_base + AS3(0)
                              + (uint32_t)row * 256u
                              + (uint32_t)((cb ^ (row & 7)) << 4);
                LDSM_X4(ah[mi][0], ah[mi][1], ah[mi][2], ah[mi][3], addr);
                LDSM_X4(al[mi][0], al[mi][1], al[mi][2], al[mi][3], addr + 32768u);
            }
            uint32_t bh[8][2], bl[8][2];
#pragma unroll
            for (int nj = 0; nj < 4; nj++) {
                int row = (ks << 4) + (lane & 15);
                int cb  = (warp_n >> 3) + (nj << 1) + (lane >> 4);
                uint32_t addr = smem_base + BS3(0)
                              + (uint32_t)row * 256u
                              + (uint32_t)((cb ^ (row & 7)) << 4);
                LDSM_X4T(bh[2*nj][0], bh[2*nj][1], bh[2*nj+1][0], bh[2*nj+1][1], addr);
                LDSM_X4T(bl[2*nj][0], bl[2*nj][1], bl[2*nj+1][0], bl[2*nj+1][1],
                         addr + 32768u);
            }
#pragma unroll
            for (int mi = 0; mi < 2; mi++)
#pragma unroll
                for (int ni = 0; ni < 8; ni++) {
                    MMA16816(acc[mi][ni], ah[mi], bh[ni]);
                    MMA16816(acc[mi][ni], ah[mi], bl[ni]);
                    MMA16816(acc[mi][ni], al[mi], bh[ni]);
                }
        }

        // epilogue: out += acc
#pragma unroll
        for (int ni = 0; ni < 8; ni++) {
            int col = warp_n + (ni << 3) + ((lane & 3) << 1);
#pragma unroll
            for (int mi = 0; mi < 2; mi++) {
                int r = warp_m + (mi << 4) + (lane >> 2);
                int node = node0 + r;
                if (node < N) {
                    float2* p = reinterpret_cast<float2*>(out + (size_t)node * D + col);
                    float2 o = *p;
                    o.x += acc[mi][ni][0]; o.y += acc[mi][ni][1];
                    *p = o;
                }
                int node2 = node + 8;
                if (node2 < N) {
                    float2* p = reinterpret_cast<float2*>(out + (size_t)node2 * D + col);
                    float2 o = *p;
                    o.x += acc[mi][ni][2]; o.y += acc[mi][ni][3];
                    *p = o;
                }
            }
        }
    }
}

// ============================================================================
// Launch
// ============================================================================
extern "C" void kernel_launch(void* const* d_in, const int* in_sizes, int n_in,
                              void* d_out, int out_size) {
    const float* x     = (const float*)d_in[0];
    const int*   esrc  = (const int*)  d_in[1];
    const int*   edst  = (const int*)  d_in[2];
    const float* eval_ = (const float*)d_in[3];
    const float* W     = (const float*)d_in[4];
    const float* bias  = (const float*)d_in[5];
    float*       out   = (float*)d_out;

    const int N = in_sizes[0] / D;     // 100000
    const int E = in_sizes[1];         // 1600000

    // 1) split x -> bf16 hi/lo, zero support, reset cursor
    {
        int n4 = N * (D / 4);
        convert_kernel<<<(n4 + 255) / 256, 256>>>(x, n4);
    }
    // 2) fused: gemm1 (out = x@W1 + b) || scatter (support += A@x)
    {
        static bool attr_set = false;
        if (!attr_set) {
            cudaFuncSetAttribute(fused_kernel,
                                 cudaFuncAttributeMaxDynamicSharedMemorySize,
                                 SM_TOTAL);
            cudaFuncSetAttribute(gemm2_kernel,
                                 cudaFuncAttributeMaxDynamicSharedMemorySize,
                                 SM3_TOTAL);
            attr_set = true;
        }
        fused_kernel<<<NCTA, GT, SM_TOTAL>>>(x, esrc, edst, eval_, W, bias,
                                             out, N, E);
    }
    // 3) out += support @ W2
    gemm2_kernel<<<NCTA, GT, SM3_TOTAL>>>(W, out, N);
}

// round 7
// speedup vs baseline: 1.5851x; 1.5851x over previous
#include <cuda_runtime.h>
#include <cuda_fp16.h>
#include <cstdint>

#define D      128      // D_IN = D_OUT
#define NMAX   100000

// Scratch (device globals; no allocation allowed)
__device__ __half g_xh[NMAX * D];   // x rounded to fp16
__device__ float  g_y [NMAX * D];   // y = x @ W2

// ============================================================================
// PTX helpers (base ISA: cp.async / ldmatrix / mma.sync)
// ============================================================================
__device__ __forceinline__ uint32_t smem_to_u32(const void* p) {
    uint32_t a;
    asm("{ .reg .u64 t; cvta.to.shared.u64 t, %1; cvt.u32.u64 %0, t; }"
        : "=r"(a) : "l"(p));
    return a;
}
#define CP_ASYNC16(dst, src, sz) \
    asm volatile("cp.async.cg.shared.global [%0], [%1], 16, %2;" \
        :: "r"(dst), "l"(src), "r"(sz))
#define CP_COMMIT() asm volatile("cp.async.commit_group;" ::: "memory")
#define CP_WAIT1()  asm volatile("cp.async.wait_group 1;"  ::: "memory")

#define LDSM_X4(r0,r1,r2,r3,addr) \
    asm volatile("ldmatrix.sync.aligned.m8n8.x4.shared.b16 {%0,%1,%2,%3}, [%4];" \
        : "=r"(r0), "=r"(r1), "=r"(r2), "=r"(r3) : "r"(addr))
#define LDSM_X4T(r0,r1,r2,r3,addr) \
    asm volatile("ldmatrix.sync.aligned.m8n8.x4.trans.shared.b16 {%0,%1,%2,%3}, [%4];" \
        : "=r"(r0), "=r"(r1), "=r"(r2), "=r"(r3) : "r"(addr))

// fp16 inputs, fp32 accumulate
#define MMA16816F16(c, a, b) \
    asm volatile("mma.sync.aligned.m16n8k16.row.col.f32.f16.f16.f32 " \
        "{%0,%1,%2,%3}, {%4,%5,%6,%7}, {%8,%9}, {%0,%1,%2,%3};" \
        : "+f"((c)[0]), "+f"((c)[1]), "+f"((c)[2]), "+f"((c)[3]) \
        : "r"((a)[0]), "r"((a)[1]), "r"((a)[2]), "r"((a)[3]), \
          "r"((b)[0]), "r"((b)[1]))

// ============================================================================
// Kernel 1: round x -> fp16 (one pass)
// ============================================================================
__global__ void convert_kernel(const float* __restrict__ x, int n4) {
    int i = blockIdx.x * blockDim.x + threadIdx.x;
    if (i >= n4) return;
    float4 v = reinterpret_cast<const float4*>(x)[i];
    __half2 h0 = __floats2half2_rn(v.x, v.y);
    __half2 h1 = __floats2half2_rn(v.z, v.w);
    reinterpret_cast<uint2*>(g_xh)[i] =
        make_uint2(*(uint32_t*)&h0, *(uint32_t*)&h1);
}

// ============================================================================
// Kernel 2: persistent GEMM via mma.sync, 2-term fp16 split (W split hi/lo)
//   (m_tile, nh): nh=0 -> d_out = x@W1 + b ; nh=1 -> g_y = x@W2
//   CTA tile 128(M) x 128(N), K=128. 8 warps, warp tile 32M x 64N.
//   SMEM: A fp16 double-buffered (2 x 32KB) + B hi/lo (2 x 32KB) = 128KB.
// ============================================================================
#define GT 256
#define AS_OFF(buf)  ((uint32_t)((buf) * 32768))
#define BS_OFF(hl)   ((uint32_t)(65536 + (hl) * 32768))
#define SM_TOTAL     131072

__device__ __forceinline__ void load_A_tile(uint32_t smem_base, int buf,
                                            int node0, int N, int tid) {
#pragma unroll
    for (int i = 0; i < 8; i++) {
        int idx  = tid + (i << 8);        // 0..2047 16B chunks
        int row  = idx >> 4;              // 0..127
        int cc   = idx & 15;              // chunk within row (8 fp16 each)
        int node = node0 + row;
        uint32_t sz    = (node < N) ? 16u : 0u;
        uint32_t chunk = (uint32_t)(cc ^ (row & 7));
        uint32_t doff  = (uint32_t)row * 256u + chunk * 16u;
        const __half* sh = g_xh + (size_t)node * D + cc * 8;
        CP_ASYNC16(smem_base + AS_OFF(buf) + doff, sh, sz);
    }
}

__global__ __launch_bounds__(GT, 1)
void gemm_kernel(const float* __restrict__ W,
                 const float* __restrict__ bias,
                 float* __restrict__ out,
                 int N) {
    extern __shared__ char smem[];
    uint32_t smem_base = smem_to_u32(smem);
    const int tid  = threadIdx.x;
    const int lane = tid & 31;
    const int wid  = tid >> 5;
    const int warp_m = (wid & 3) << 5;
    const int warp_n = (wid >> 2) << 6;

    const int num_tiles = (N + 127) >> 7;
    const int total = num_tiles * 2;
    int cur_nh = -1;

    int item = blockIdx.x;
    int buf = 0;
    if (item < total) load_A_tile(smem_base, 0, (item % num_tiles) << 7, N, tid);
    CP_COMMIT();

    for (; item < total; item += gridDim.x) {
        const int m_tile = item % num_tiles;
        const int nh     = item / num_tiles;
        const int node0  = m_tile << 7;

        int next = item + gridDim.x;
        if (next < total)
            load_A_tile(smem_base, buf ^ 1, (next % num_tiles) << 7, N, tid);
        CP_COMMIT();

        // (re)load B = W[nh*128 : +128][:] split into fp16 hi/lo
        if (nh != cur_nh) {
            cur_nh = nh;
#pragma unroll
            for (int j = 0; j < 32; j++) {
                int idx = tid + (j << 8);          // 0..8191 (half2 pairs)
                int k   = idx >> 6;                // 0..127
                int n   = (idx & 63) << 1;         // even col
                const float* wp = W + ((size_t)(nh * 128 + k)) * 128 + n;
                float w0 = wp[0], w1 = wp[1];
                __half2 h = __floats2half2_rn(w0, w1);
                float q0 = w0 - __half2float(__low2half(h));
                float q1 = w1 - __half2float(__high2half(h));
                __half2 l = __floats2half2_rn(q0, q1);
                uint32_t boff = (uint32_t)k * 256u
                              + (uint32_t)(((n >> 3) ^ (k & 7)) << 4)
                              + (uint32_t)((n & 7) << 1);
                *reinterpret_cast<uint32_t*>(smem + BS_OFF(0) + boff) = *(uint32_t*)&h;
                *reinterpret_cast<uint32_t*>(smem + BS_OFF(1) + boff) = *(uint32_t*)&l;
            }
        }

        CP_WAIT1();
        __syncthreads();     // A(buf) ready + B visible

        float acc[2][8][4];
#pragma unroll
        for (int mi = 0; mi < 2; mi++)
#pragma unroll
            for (int ni = 0; ni < 8; ni++)
#pragma unroll
                for (int q = 0; q < 4; q++) acc[mi][ni][q] = 0.f;

#pragma unroll
        for (int ks = 0; ks < 8; ks++) {
            uint32_t ah[2][4];
#pragma unroll
            for (int mi = 0; mi < 2; mi++) {
                int row = warp_m + (mi << 4) + (lane & 15);
                int cb  = (ks << 1) + (lane >> 4);
                uint32_t addr = smem_base + AS_OFF(buf)
                              + (uint32_t)row * 256u
                              + (uint32_t)((cb ^ (row & 7)) << 4);
                LDSM_X4(ah[mi][0], ah[mi][1], ah[mi][2], ah[mi][3], addr);
            }
            uint32_t bh[8][2], bl[8][2];
#pragma unroll
            for (int nj = 0; nj < 4; nj++) {
                int row = (ks << 4) + (lane & 15);
                int cb  = (warp_n >> 3) + (nj << 1) + (lane >> 4);
                uint32_t addr = smem_base + BS_OFF(0)
                              + (uint32_t)row * 256u
                              + (uint32_t)((cb ^ (row & 7)) << 4);
                LDSM_X4T(bh[2*nj][0], bh[2*nj][1], bh[2*nj+1][0], bh[2*nj+1][1], addr);
                LDSM_X4T(bl[2*nj][0], bl[2*nj][1], bl[2*nj+1][0], bl[2*nj+1][1],
                         addr + 32768u);
            }
#pragma unroll
            for (int mi = 0; mi < 2; mi++)
#pragma unroll
                for (int ni = 0; ni < 8; ni++) {
                    MMA16816F16(acc[mi][ni], ah[mi], bh[ni]);   // Ah*Bh
                    MMA16816F16(acc[mi][ni], ah[mi], bl[ni]);   // Ah*Bl
                }
        }

        float* dst = (nh == 0) ? out : g_y;
#pragma unroll
        for (int ni = 0; ni < 8; ni++) {
            int col = warp_n + (ni << 3) + ((lane & 3) << 1);
            float b0 = 0.f, b1 = 0.f;
            if (nh == 0) { b0 = bias[col]; b1 = bias[col + 1]; }
#pragma unroll
            for (int mi = 0; mi < 2; mi++) {
                int r = warp_m + (mi << 4) + (lane >> 2);
                int node = node0 + r;
                if (node < N) {
                    float2 v = make_float2(acc[mi][ni][0] + b0, acc[mi][ni][1] + b1);
                    *reinterpret_cast<float2*>(dst + (size_t)node * D + col) = v;
                }
                int node2 = node + 8;
                if (node2 < N) {
                    float2 v = make_float2(acc[mi][ni][2] + b0, acc[mi][ni][3] + b1);
                    *reinterpret_cast<float2*>(dst + (size_t)node2 * D + col) = v;
                }
            }
        }
        __syncthreads();
        buf ^= 1;
    }
}

// ============================================================================
// Kernel 3: edge scatter (warp per edge — the proven R3 shape):
//   out[dst] += val * y[src]  via red.global.add.v4.f32
// ============================================================================
__global__ void scatter_kernel(const int*   __restrict__ esrc,
                               const int*   __restrict__ edst,
                               const float* __restrict__ eval_,
                               float* __restrict__ out,
                               int E) {
    int warp = (blockIdx.x * blockDim.x + threadIdx.x) >> 5;
    int lane = threadIdx.x & 31;
    if (warp >= E) return;

    int   s = esrc[warp];
    int   d = edst[warp];
    float v = eval_[warp];

    const float4* ys = reinterpret_cast<const float4*>(g_y) + (size_t)s * (D / 4);
    float4 yv = ys[lane];
    float4 r  = make_float4(yv.x * v, yv.y * v, yv.z * v, yv.w * v);

    float* p = out + (size_t)d * D + lane * 4;
    asm volatile("red.global.add.v4.f32 [%0], {%1, %2, %3, %4};"
                 :: "l"(p), "f"(r.x), "f"(r.y), "f"(r.z), "f"(r.w)
                 : "memory");
}

// ============================================================================
// Launch
// ============================================================================
extern "C" void kernel_launch(void* const* d_in, const int* in_sizes, int n_in,
                              void* d_out, int out_size) {
    const float* x     = (const float*)d_in[0];
    const int*   esrc  = (const int*)  d_in[1];
    const int*   edst  = (const int*)  d_in[2];
    const float* eval_ = (const float*)d_in[3];
    const float* W     = (const float*)d_in[4];
    const float* bias  = (const float*)d_in[5];
    float*       out   = (float*)d_out;

    const int N = in_sizes[0] / D;     // 100000
    const int E = in_sizes[1];         // 1600000

    // 1) round x -> fp16
    {
        int n4 = N * (D / 4);
        convert_kernel<<<(n4 + 255) / 256, 256>>>(x, n4);
    }
    // 2) persistent GEMM: d_out = x@W1 + b ; g_y = x@W2
    {
        static bool attr_set = false;
        if (!attr_set) {
            cudaFuncSetAttribute(gemm_kernel,
                                 cudaFuncAttributeMaxDynamicSharedMemorySize,
                                 SM_TOTAL);
            attr_set = true;
        }
        gemm_kernel<<<148, GT, SM_TOTAL>>>(W, bias, out, N);
    }
    // 3) scatter-add edges into d_out (warp per edge)
    {
        int blocks = (E + 7) / 8;      // 8 warps (256 thr) per block
        scatter_kernel<<<blocks, 256>>>(esrc, edst, eval_, out, E);
    }
}